// round 14
// baseline (speedup 1.0000x reference)
#include <cuda_runtime.h>
#include <cuda_fp16.h>
#include <cstdint>
#include <math.h>

#define NMAX 100000
#define EMAX 1600000
#define DIM  128
#define NG   128

typedef unsigned int u32;

// ---------------- scratch (device globals) ------------------------------------
__device__ __half g_H16[(size_t)NMAX * DIM];    // H' = (X@W) * dinv  (fp16)
__device__ __half g_AGG16[(size_t)NMAX * DIM];  // aggregated pre-bias/relu (fp16)
__device__ __half g_W16[3 * DIM * DIM];         // W (fp16)
__device__ float g_dinv[NMAX];
__device__ int   g_deg[NMAX];
__device__ int   g_fill[NMAX];
__device__ int   g_rowptr[NMAX + 1];
__device__ int   g_bsum[512];
__device__ int   g_csr[EMAX];
__device__ float g_sums[NG * DIM];
__device__ float g_cnt[NG];

// ---------------- fused prep: cvt W, zero deg/fill/sums/cnt --------------------
__global__ void k_prep0(const float* __restrict__ w, int nw, int n) {
    int i = blockIdx.x * blockDim.x + threadIdx.x;
    if (i < nw) g_W16[i] = __float2half_rn(w[i]);
    if (i < n) { g_deg[i] = 0; g_fill[i] = 0; }
    if (i < NG * DIM) g_sums[i] = 0.f;
    if (i < NG) g_cnt[i] = 0.f;
}
__global__ void k_deg(const int* __restrict__ dst, int E) {
    int e = blockIdx.x * blockDim.x + threadIdx.x;
    if (e < E) atomicAdd(&g_deg[dst[e]], 1);
}

// ---------------- scan1 (+ fused dinv) -----------------------------------------
__global__ __launch_bounds__(512) void k_scan1(int n) {
    __shared__ int wsum[16];
    int id = blockIdx.x * 512 + threadIdx.x;
    int lane = threadIdx.x & 31, w = threadIdx.x >> 5;
    int v = (id < n) ? g_deg[id] : 0;
    if (id < n) g_dinv[id] = rsqrtf((float)(v + 1));   // fused normalization
    int incl = v;
#pragma unroll
    for (int o = 1; o < 32; o <<= 1) {
        int t = __shfl_up_sync(~0u, incl, o);
        if (lane >= o) incl += t;
    }
    if (lane == 31) wsum[w] = incl;
    __syncthreads();
    if (w == 0) {
        int s = (lane < 16) ? wsum[lane] : 0;
#pragma unroll
        for (int o = 1; o < 16; o <<= 1) {
            int t = __shfl_up_sync(~0u, s, o);
            if (lane >= o) s += t;
        }
        if (lane < 16) wsum[lane] = s;
    }
    __syncthreads();
    int woff = (w > 0) ? wsum[w - 1] : 0;
    if (id < n) g_rowptr[id] = woff + incl - v;
    if (threadIdx.x == 511) g_bsum[blockIdx.x] = wsum[15];
}
__global__ __launch_bounds__(256) void k_scan2(int nb) {
    __shared__ int wsum[8];
    int tid = threadIdx.x, lane = tid & 31, w = tid >> 5;
    int v = (tid < nb) ? g_bsum[tid] : 0;
    int incl = v;
#pragma unroll
    for (int o = 1; o < 32; o <<= 1) {
        int t = __shfl_up_sync(~0u, incl, o);
        if (lane >= o) incl += t;
    }
    if (lane == 31) wsum[w] = incl;
    __syncthreads();
    if (w == 0) {
        int s = (lane < 8) ? wsum[lane] : 0;
#pragma unroll
        for (int o = 1; o < 8; o <<= 1) {
            int t = __shfl_up_sync(~0u, s, o);
            if (lane >= o) s += t;
        }
        if (lane < 8) wsum[lane] = s;
    }
    __syncthreads();
    int woff = (w > 0) ? wsum[w - 1] : 0;
    if (tid < nb) g_bsum[tid] = woff + incl - v;
}
__global__ __launch_bounds__(512) void k_scan3(int n, int E) {
    int id = blockIdx.x * 512 + threadIdx.x;
    if (id < n) g_rowptr[id] += g_bsum[blockIdx.x];
    if (id == 0) g_rowptr[n] = E;
}
__global__ void k_fill(const int* __restrict__ src, const int* __restrict__ dst, int E) {
    int e = blockIdx.x * blockDim.x + threadIdx.x;
    if (e < E) {
        int d = dst[e];
        int pos = g_rowptr[d] + atomicAdd(&g_fill[d], 1);
        g_csr[pos] = src[e];
    }
}

// ---------------- tensor-core GEMM helpers ------------------------------------
#define ASTRIDE 40
#define BSTRIDE 136

__device__ __forceinline__ void ldsm4(u32 r[4], u32 addr) {
    asm volatile("ldmatrix.sync.aligned.m8n8.x4.shared.b16 {%0,%1,%2,%3}, [%4];"
                 : "=r"(r[0]), "=r"(r[1]), "=r"(r[2]), "=r"(r[3]) : "r"(addr));
}
__device__ __forceinline__ void ldsm4t(u32 r[4], u32 addr) {
    asm volatile("ldmatrix.sync.aligned.m8n8.x4.trans.shared.b16 {%0,%1,%2,%3}, [%4];"
                 : "=r"(r[0]), "=r"(r[1]), "=r"(r[2]), "=r"(r[3]) : "r"(addr));
}
__device__ __forceinline__ void mma16816(float c[4], const u32 a[4], u32 b0, u32 b1) {
    asm volatile("mma.sync.aligned.m16n8k16.row.col.f32.f16.f16.f32 "
                 "{%0,%1,%2,%3}, {%4,%5,%6,%7}, {%8,%9}, {%0,%1,%2,%3};"
                 : "+f"(c[0]), "+f"(c[1]), "+f"(c[2]), "+f"(c[3])
                 : "r"(a[0]), "r"(a[1]), "r"(a[2]), "r"(a[3]), "r"(b0), "r"(b1));
}
__device__ __forceinline__ void cpasync16(u32 dst, const void* src) {
    asm volatile("cp.async.ca.shared.global [%0], [%1], 16;" :: "r"(dst), "l"(src));
}

// H' = relu(pre(X)) @ W * dinv ; fp16 MMA, fp32 accumulate.
// Software-pipelined: double-buffered smem, cp.async B, register-prefetched A.
__global__ __launch_bounds__(256, 2) void k_gemm_mma(
    const float* __restrict__ Xext, int layer,
    const float* __restrict__ bias, int useAgg, int M)
{
    __shared__ alignas(16) __half sA[2][128 * ASTRIDE];
    __shared__ alignas(16) __half sB[2][32 * BSTRIDE];

    const __half* W = g_W16 + (size_t)layer * DIM * DIM;

    int tid  = threadIdx.x;
    int lane = tid & 31, warp = tid >> 5;
    int m0   = blockIdx.x * 128;
    int grp  = lane >> 2, tig = lane & 3;

    int sub  = lane >> 3;
    int lrow = (lane & 7) + ((sub & 1) << 3);
    int lcol = (sub >> 1) << 3;

    float acc[16][4];
#pragma unroll
    for (int nt = 0; nt < 16; nt++)
#pragma unroll
        for (int c = 0; c < 4; c++) acc[nt][c] = 0.f;

    float4 rf[4];
    uint2  rh[4];

    auto issueA = [&](int kc) {
#pragma unroll
        for (int i = 0; i < 4; i++) {
            int f   = tid + (i << 8);
            int row = f >> 3;
            int c   = (f & 7) << 2;
            int gr  = m0 + row;
            if (useAgg) {
                rh[i] = make_uint2(0u, 0u);
                if (gr < M)
                    rh[i] = *reinterpret_cast<const uint2*>(
                        &g_AGG16[(size_t)gr * DIM + kc * 32 + c]);
            } else {
                rf[i] = make_float4(0.f, 0.f, 0.f, 0.f);
                if (gr < M)
                    rf[i] = *reinterpret_cast<const float4*>(
                        Xext + (size_t)gr * DIM + kc * 32 + c);
            }
        }
    };
    auto convA = [&](int kc, int p) {
#pragma unroll
        for (int i = 0; i < 4; i++) {
            int f   = tid + (i << 8);
            int row = f >> 3;
            int c   = (f & 7) << 2;
            float4 v;
            if (useAgg) {
                float2 f0 = __half22float2(*reinterpret_cast<__half2*>(&rh[i].x));
                float2 f1 = __half22float2(*reinterpret_cast<__half2*>(&rh[i].y));
                v.x = fmaxf(f0.x + bias[kc * 32 + c + 0], 0.f);
                v.y = fmaxf(f0.y + bias[kc * 32 + c + 1], 0.f);
                v.z = fmaxf(f1.x + bias[kc * 32 + c + 2], 0.f);
                v.w = fmaxf(f1.y + bias[kc * 32 + c + 3], 0.f);
            } else {
                v = rf[i];
            }
            int base = row * ASTRIDE + c;
            *reinterpret_cast<__half2*>(&sA[p][base + 0]) = __floats2half2_rn(v.x, v.y);
            *reinterpret_cast<__half2*>(&sA[p][base + 2]) = __floats2half2_rn(v.z, v.w);
        }
    };
    auto issueB = [&](int kc, int p) {
        int row = tid >> 3;
        int c   = (tid & 7) << 4;
        const __half* gsrc = W + (size_t)(kc * 32 + row) * DIM + c;
        u32 d0 = (u32)__cvta_generic_to_shared(&sB[p][row * BSTRIDE + c]);
        cpasync16(d0, gsrc);
        cpasync16(d0 + 16, gsrc + 8);
        asm volatile("cp.async.commit_group;");
    };

    issueB(0, 0);
    issueA(0);
    convA(0, 0);
    asm volatile("cp.async.wait_group 0;" ::: "memory");
    __syncthreads();

    int p = 0;
    for (int kc = 0; kc < 4; kc++) {
        if (kc < 3) {
            issueB(kc + 1, p ^ 1);
            issueA(kc + 1);
        }
#pragma unroll
        for (int ks = 0; ks < 2; ks++) {
            u32 fragA[4];
            ldsm4(fragA, (u32)__cvta_generic_to_shared(
                &sA[p][(16 * warp + lrow) * ASTRIDE + 16 * ks + lcol]));
#pragma unroll
            for (int n0 = 0; n0 < 8; n0++) {
                u32 fragB[4];
                ldsm4t(fragB, (u32)__cvta_generic_to_shared(
                    &sB[p][(16 * ks + lrow) * BSTRIDE + 16 * n0 + lcol]));
                mma16816(acc[2 * n0],     fragA, fragB[0], fragB[1]);
                mma16816(acc[2 * n0 + 1], fragA, fragB[2], fragB[3]);
            }
        }
        if (kc < 3) {
            convA(kc + 1, p ^ 1);
            asm volatile("cp.async.wait_group 0;" ::: "memory");
            __syncthreads();
            p ^= 1;
        }
    }

    int r0 = m0 + 16 * warp + grp;
    int r1 = r0 + 8;
    float d0 = (r0 < M) ? g_dinv[r0] : 0.f;
    float d1 = (r1 < M) ? g_dinv[r1] : 0.f;
#pragma unroll
    for (int nt = 0; nt < 16; nt++) {
        int col = 8 * nt + 2 * tig;
        if (r0 < M) {
            __half2 h = __floats2half2_rn(acc[nt][0] * d0, acc[nt][1] * d0);
            *reinterpret_cast<__half2*>(&g_H16[(size_t)r0 * DIM + col]) = h;
        }
        if (r1 < M) {
            __half2 h = __floats2half2_rn(acc[nt][2] * d1, acc[nt][3] * d1);
            *reinterpret_cast<__half2*>(&g_H16[(size_t)r1 * DIM + col]) = h;
        }
    }
}

// ---------------- gather: AGG[d] = dinv[d] * (sum H'[src] + H'[d]) ------------
__device__ __forceinline__ void acc_row(float4& acc, uint2 raw) {
    float2 f0 = __half22float2(*reinterpret_cast<__half2*>(&raw.x));
    float2 f1 = __half22float2(*reinterpret_cast<__half2*>(&raw.y));
    acc.x += f0.x; acc.y += f0.y; acc.z += f1.x; acc.w += f1.y;
}
__global__ __launch_bounds__(256) void k_gather(int N) {
    int warp = (blockIdx.x * blockDim.x + threadIdx.x) >> 5;
    if (warp >= N) return;
    int lane = threadIdx.x & 31;

    const uint2* Hv = reinterpret_cast<const uint2*>(g_H16);
    int beg = g_rowptr[warp];
    int end = g_rowptr[warp + 1];

    float4 acc = make_float4(0.f, 0.f, 0.f, 0.f);
    acc_row(acc, Hv[(size_t)warp * 32 + lane]);

    int e = beg;
    for (; e + 4 <= end; e += 4) {
        int s0 = g_csr[e], s1 = g_csr[e + 1], s2 = g_csr[e + 2], s3 = g_csr[e + 3];
        uint2 r0 = Hv[(size_t)s0 * 32 + lane];
        uint2 r1 = Hv[(size_t)s1 * 32 + lane];
        uint2 r2 = Hv[(size_t)s2 * 32 + lane];
        uint2 r3 = Hv[(size_t)s3 * 32 + lane];
        acc_row(acc, r0); acc_row(acc, r1); acc_row(acc, r2); acc_row(acc, r3);
    }
    for (; e < end; e++)
        acc_row(acc, Hv[(size_t)g_csr[e] * 32 + lane]);

    float di = g_dinv[warp];
    __half2 h0 = __floats2half2_rn(acc.x * di, acc.y * di);
    __half2 h1 = __floats2half2_rn(acc.z * di, acc.w * di);
    uint2 outv;
    outv.x = *reinterpret_cast<u32*>(&h0);
    outv.y = *reinterpret_cast<u32*>(&h1);
    reinterpret_cast<uint2*>(g_AGG16)[(size_t)warp * 32 + lane] = outv;
}

// ---------------- pooling (run-length, batch sorted) --------------------------
#define PCHUNK 32
__global__ __launch_bounds__(256) void k_pool(const int* __restrict__ batch,
                                              const float* __restrict__ bias, int n) {
    int warp = (blockIdx.x * blockDim.x + threadIdx.x) >> 5;
    int lane = threadIdx.x & 31;
    int q = lane * 4;
    int n0 = warp * PCHUNK;
    if (n0 >= n) return;
    int n1 = min(n0 + PCHUNK, n);

    float b0 = bias[q], b1 = bias[q + 1], b2 = bias[q + 2], b3 = bias[q + 3];
    const uint2* Av = reinterpret_cast<const uint2*>(g_AGG16);

    float4 acc = make_float4(0.f, 0.f, 0.f, 0.f);
    float cnt = 0.f;
    int cur = batch[n0];
    for (int node = n0; node < n1; node++) {
        int bb = batch[node];
        if (bb != cur) {
            float* p = &g_sums[cur * DIM + q];
            asm volatile("red.global.add.v4.f32 [%0], {%1, %2, %3, %4};"
                         :: "l"(p), "f"(acc.x), "f"(acc.y), "f"(acc.z), "f"(acc.w) : "memory");
            if (lane == 0) atomicAdd(&g_cnt[cur], cnt);
            acc = make_float4(0.f, 0.f, 0.f, 0.f);
            cnt = 0.f;
            cur = bb;
        }
        uint2 raw = Av[(size_t)node * 32 + lane];
        float2 f0 = __half22float2(*reinterpret_cast<__half2*>(&raw.x));
        float2 f1 = __half22float2(*reinterpret_cast<__half2*>(&raw.y));
        acc.x += fmaxf(f0.x + b0, 0.f);
        acc.y += fmaxf(f0.y + b1, 0.f);
        acc.z += fmaxf(f1.x + b2, 0.f);
        acc.w += fmaxf(f1.y + b3, 0.f);
        cnt += 1.f;
    }
    float* p = &g_sums[cur * DIM + q];
    asm volatile("red.global.add.v4.f32 [%0], {%1, %2, %3, %4};"
                 :: "l"(p), "f"(acc.x), "f"(acc.y), "f"(acc.z), "f"(acc.w) : "memory");
    if (lane == 0) atomicAdd(&g_cnt[cur], cnt);
}

// ---------------- fused head: lin1 + relu + lin2 + log_softmax -----------------
__global__ void k_lin1head(const float* __restrict__ w1, const float* __restrict__ b1,
                           const float* __restrict__ w2, const float* __restrict__ b2,
                           float* __restrict__ out) {
    int g = blockIdx.x;       // 128 graphs
    int j = threadIdx.x;      // 128 dims
    __shared__ float srow[DIM];
    __shared__ float red0[DIM];
    __shared__ float red1[DIM];
    float inv = 1.0f / fmaxf(g_cnt[g], 1.0f);
    srow[j] = g_sums[g * DIM + j] * inv;
    __syncthreads();
    float acc = b1[j];
#pragma unroll 8
    for (int k = 0; k < DIM; k++) acc += srow[k] * w1[k * DIM + j];
    float h = fmaxf(acc, 0.f);
    red0[j] = h * w2[j * 2 + 0];
    red1[j] = h * w2[j * 2 + 1];
    __syncthreads();
#pragma unroll
    for (int s = 64; s > 0; s >>= 1) {
        if (j < s) { red0[j] += red0[j + s]; red1[j] += red1[j + s]; }
        __syncthreads();
    }
    if (j == 0) {
        float l0 = red0[0] + b2[0];
        float l1 = red1[0] + b2[1];
        float m   = fmaxf(l0, l1);
        float lse = m + logf(expf(l0 - m) + expf(l1 - m));
        out[g * 2 + 0] = l0 - lse;
        out[g * 2 + 1] = l1 - lse;
    }
}

// ---------------- launch ------------------------------------------------------
extern "C" void kernel_launch(void* const* d_in, const int* in_sizes, int n_in,
                              void* d_out, int out_size) {
    const float* x      = (const float*)d_in[0];
    const int*   ei     = (const int*)d_in[1];
    const int*   batch  = (const int*)d_in[2];
    const float* conv_w = (const float*)d_in[3];
    const float* conv_b = (const float*)d_in[4];
    const float* lin1_w = (const float*)d_in[5];
    const float* lin1_b = (const float*)d_in[6];
    const float* lin2_w = (const float*)d_in[7];
    const float* lin2_b = (const float*)d_in[8];
    float* out = (float*)d_out;

    int N = in_sizes[2];
    int E = in_sizes[1] / 2;
    const int* src = ei;
    const int* dst = ei + E;

    int prep_max = (3 * DIM * DIM > N) ? 3 * DIM * DIM : N;
    k_prep0<<<(prep_max + 255) / 256, 256>>>(conv_w, 3 * DIM * DIM, N);
    k_deg<<<(E + 255) / 256, 256>>>(dst, E);

    int nb = (N + 511) / 512;
    k_scan1<<<nb, 512>>>(N);
    k_scan2<<<1, 256>>>(nb);
    k_scan3<<<nb, 512>>>(N, E);
    k_fill<<<(E + 255) / 256, 256>>>(src, dst, E);

    int gemm_blocks   = (N + 127) / 128;
    int gather_blocks = (N * 32 + 255) / 256;

    for (int l = 0; l < 3; l++) {
        const float* bias = (l > 0) ? (conv_b + (size_t)(l - 1) * DIM) : conv_b;
        k_gemm_mma<<<gemm_blocks, 256>>>(x, l, bias, l > 0 ? 1 : 0, N);
        k_gather<<<gather_blocks, 256>>>(N);
    }

    int pool_warps = (N + PCHUNK - 1) / PCHUNK;
    k_pool<<<(pool_warps * 32 + 255) / 256, 256>>>(batch, conv_b + (size_t)2 * DIM, N);
    k_lin1head<<<NG, DIM>>>(lin1_w, lin1_b, lin2_w, lin2_b, out);
}

// round 15
// speedup vs baseline: 1.3866x; 1.3866x over previous
#include <cuda_runtime.h>
#include <cuda_fp16.h>
#include <cstdint>
#include <math.h>

#define NMAX 100000
#define EMAX 1600000
#define DIM  128
#define NG   128

typedef unsigned int u32;

// ---------------- scratch (device globals) ------------------------------------
__device__ __half g_H16[(size_t)NMAX * DIM];    // H' = (X@W) * dinv  (fp16)
__device__ __half g_AGG16[(size_t)NMAX * DIM];  // aggregated pre-bias/relu (fp16)
__device__ __half g_W16[3 * DIM * DIM];         // W (fp16)
__device__ float g_dinv[NMAX];
__device__ int   g_deg[NMAX];
__device__ int   g_fill[NMAX];
__device__ int   g_rowptr[NMAX + 1];
__device__ int   g_bsum[512];
__device__ int   g_csr[EMAX];
__device__ float g_sums[NG * DIM];
__device__ float g_cnt[NG];
__device__ float g_G1[NG * DIM];

// ---------------- prep kernels -------------------------------------------------
__global__ void k_zero_deg(int n) {
    int i = blockIdx.x * blockDim.x + threadIdx.x;
    if (i < n) { g_deg[i] = 0; g_fill[i] = 0; }
}
__global__ void k_deg(const int* __restrict__ dst, int E) {
    int e = blockIdx.x * blockDim.x + threadIdx.x;
    if (e < E) atomicAdd(&g_deg[dst[e]], 1);
}
__global__ void k_cvtw(const float* __restrict__ w, int n) {
    int i = blockIdx.x * blockDim.x + threadIdx.x;
    if (i < n) g_W16[i] = __float2half_rn(w[i]);
}

// ---------------- scan1 (+ fused dinv) -----------------------------------------
__global__ __launch_bounds__(512) void k_scan1(int n) {
    __shared__ int wsum[16];
    int id = blockIdx.x * 512 + threadIdx.x;
    int lane = threadIdx.x & 31, w = threadIdx.x >> 5;
    int v = (id < n) ? g_deg[id] : 0;
    if (id < n) g_dinv[id] = rsqrtf((float)(v + 1));   // fused normalization
    int incl = v;
#pragma unroll
    for (int o = 1; o < 32; o <<= 1) {
        int t = __shfl_up_sync(~0u, incl, o);
        if (lane >= o) incl += t;
    }
    if (lane == 31) wsum[w] = incl;
    __syncthreads();
    if (w == 0) {
        int s = (lane < 16) ? wsum[lane] : 0;
#pragma unroll
        for (int o = 1; o < 16; o <<= 1) {
            int t = __shfl_up_sync(~0u, s, o);
            if (lane >= o) s += t;
        }
        if (lane < 16) wsum[lane] = s;
    }
    __syncthreads();
    int woff = (w > 0) ? wsum[w - 1] : 0;
    if (id < n) g_rowptr[id] = woff + incl - v;
    if (threadIdx.x == 511) g_bsum[blockIdx.x] = wsum[15];
}
__global__ __launch_bounds__(256) void k_scan2(int nb) {
    __shared__ int wsum[8];
    int tid = threadIdx.x, lane = tid & 31, w = tid >> 5;
    int v = (tid < nb) ? g_bsum[tid] : 0;
    int incl = v;
#pragma unroll
    for (int o = 1; o < 32; o <<= 1) {
        int t = __shfl_up_sync(~0u, incl, o);
        if (lane >= o) incl += t;
    }
    if (lane == 31) wsum[w] = incl;
    __syncthreads();
    if (w == 0) {
        int s = (lane < 8) ? wsum[lane] : 0;
#pragma unroll
        for (int o = 1; o < 8; o <<= 1) {
            int t = __shfl_up_sync(~0u, s, o);
            if (lane >= o) s += t;
        }
        if (lane < 8) wsum[lane] = s;
    }
    __syncthreads();
    int woff = (w > 0) ? wsum[w - 1] : 0;
    if (tid < nb) g_bsum[tid] = woff + incl - v;
}
__global__ __launch_bounds__(512) void k_scan3(int n, int E) {
    int id = blockIdx.x * 512 + threadIdx.x;
    if (id < n) g_rowptr[id] += g_bsum[blockIdx.x];
    if (id == 0) g_rowptr[n] = E;
}
__global__ void k_fill(const int* __restrict__ src, const int* __restrict__ dst, int E) {
    int e = blockIdx.x * blockDim.x + threadIdx.x;
    if (e < E) {
        int d = dst[e];
        int pos = g_rowptr[d] + atomicAdd(&g_fill[d], 1);
        g_csr[pos] = src[e];
    }
}

// ---------------- tensor-core GEMM helpers ------------------------------------
#define ASTRIDE 40
#define BSTRIDE 136

__device__ __forceinline__ void ldsm4(u32 r[4], u32 addr) {
    asm volatile("ldmatrix.sync.aligned.m8n8.x4.shared.b16 {%0,%1,%2,%3}, [%4];"
                 : "=r"(r[0]), "=r"(r[1]), "=r"(r[2]), "=r"(r[3]) : "r"(addr));
}
__device__ __forceinline__ void ldsm4t(u32 r[4], u32 addr) {
    asm volatile("ldmatrix.sync.aligned.m8n8.x4.trans.shared.b16 {%0,%1,%2,%3}, [%4];"
                 : "=r"(r[0]), "=r"(r[1]), "=r"(r[2]), "=r"(r[3]) : "r"(addr));
}
__device__ __forceinline__ void mma16816(float c[4], const u32 a[4], u32 b0, u32 b1) {
    asm volatile("mma.sync.aligned.m16n8k16.row.col.f32.f16.f16.f32 "
                 "{%0,%1,%2,%3}, {%4,%5,%6,%7}, {%8,%9}, {%0,%1,%2,%3};"
                 : "+f"(c[0]), "+f"(c[1]), "+f"(c[2]), "+f"(c[3])
                 : "r"(a[0]), "r"(a[1]), "r"(a[2]), "r"(a[3]), "r"(b0), "r"(b1));
}
__device__ __forceinline__ void cpasync16(u32 dst, const void* src) {
    asm volatile("cp.async.ca.shared.global [%0], [%1], 16;" :: "r"(dst), "l"(src));
}

// H' = relu(pre(X)) @ W * dinv ; fp16 MMA, fp32 accumulate.
// Software-pipelined: double-buffered smem, cp.async B, register-prefetched A.
__global__ __launch_bounds__(256, 2) void k_gemm_mma(
    const float* __restrict__ Xext, int layer,
    const float* __restrict__ bias, int useAgg, int M)
{
    __shared__ alignas(16) __half sA[2][128 * ASTRIDE];
    __shared__ alignas(16) __half sB[2][32 * BSTRIDE];

    const __half* W = g_W16 + (size_t)layer * DIM * DIM;

    int tid  = threadIdx.x;
    int lane = tid & 31, warp = tid >> 5;
    int m0   = blockIdx.x * 128;
    int grp  = lane >> 2, tig = lane & 3;

    int sub  = lane >> 3;
    int lrow = (lane & 7) + ((sub & 1) << 3);
    int lcol = (sub >> 1) << 3;

    float acc[16][4];
#pragma unroll
    for (int nt = 0; nt < 16; nt++)
#pragma unroll
        for (int c = 0; c < 4; c++) acc[nt][c] = 0.f;

    float4 rf[4];
    uint2  rh[4];

    auto issueA = [&](int kc) {
#pragma unroll
        for (int i = 0; i < 4; i++) {
            int f   = tid + (i << 8);
            int row = f >> 3;
            int c   = (f & 7) << 2;
            int gr  = m0 + row;
            if (useAgg) {
                rh[i] = make_uint2(0u, 0u);
                if (gr < M)
                    rh[i] = *reinterpret_cast<const uint2*>(
                        &g_AGG16[(size_t)gr * DIM + kc * 32 + c]);
            } else {
                rf[i] = make_float4(0.f, 0.f, 0.f, 0.f);
                if (gr < M)
                    rf[i] = *reinterpret_cast<const float4*>(
                        Xext + (size_t)gr * DIM + kc * 32 + c);
            }
        }
    };
    auto convA = [&](int kc, int p) {
#pragma unroll
        for (int i = 0; i < 4; i++) {
            int f   = tid + (i << 8);
            int row = f >> 3;
            int c   = (f & 7) << 2;
            float4 v;
            if (useAgg) {
                float2 f0 = __half22float2(*reinterpret_cast<__half2*>(&rh[i].x));
                float2 f1 = __half22float2(*reinterpret_cast<__half2*>(&rh[i].y));
                v.x = fmaxf(f0.x + bias[kc * 32 + c + 0], 0.f);
                v.y = fmaxf(f0.y + bias[kc * 32 + c + 1], 0.f);
                v.z = fmaxf(f1.x + bias[kc * 32 + c + 2], 0.f);
                v.w = fmaxf(f1.y + bias[kc * 32 + c + 3], 0.f);
            } else {
                v = rf[i];
            }
            int base = row * ASTRIDE + c;
            *reinterpret_cast<__half2*>(&sA[p][base + 0]) = __floats2half2_rn(v.x, v.y);
            *reinterpret_cast<__half2*>(&sA[p][base + 2]) = __floats2half2_rn(v.z, v.w);
        }
    };
    auto issueB = [&](int kc, int p) {
        int row = tid >> 3;
        int c   = (tid & 7) << 4;
        const __half* gsrc = W + (size_t)(kc * 32 + row) * DIM + c;
        u32 d0 = (u32)__cvta_generic_to_shared(&sB[p][row * BSTRIDE + c]);
        cpasync16(d0, gsrc);
        cpasync16(d0 + 16, gsrc + 8);
        asm volatile("cp.async.commit_group;");
    };

    issueB(0, 0);
    issueA(0);
    convA(0, 0);
    asm volatile("cp.async.wait_group 0;" ::: "memory");
    __syncthreads();

    int p = 0;
    for (int kc = 0; kc < 4; kc++) {
        if (kc < 3) {
            issueB(kc + 1, p ^ 1);
            issueA(kc + 1);
        }
#pragma unroll
        for (int ks = 0; ks < 2; ks++) {
            u32 fragA[4];
            ldsm4(fragA, (u32)__cvta_generic_to_shared(
                &sA[p][(16 * warp + lrow) * ASTRIDE + 16 * ks + lcol]));
#pragma unroll
            for (int n0 = 0; n0 < 8; n0++) {
                u32 fragB[4];
                ldsm4t(fragB, (u32)__cvta_generic_to_shared(
                    &sB[p][(16 * ks + lrow) * BSTRIDE + 16 * n0 + lcol]));
                mma16816(acc[2 * n0],     fragA, fragB[0], fragB[1]);
                mma16816(acc[2 * n0 + 1], fragA, fragB[2], fragB[3]);
            }
        }
        if (kc < 3) {
            convA(kc + 1, p ^ 1);
            asm volatile("cp.async.wait_group 0;" ::: "memory");
            __syncthreads();
            p ^= 1;
        }
    }

    int r0 = m0 + 16 * warp + grp;
    int r1 = r0 + 8;
    float d0 = (r0 < M) ? g_dinv[r0] : 0.f;
    float d1 = (r1 < M) ? g_dinv[r1] : 0.f;
#pragma unroll
    for (int nt = 0; nt < 16; nt++) {
        int col = 8 * nt + 2 * tig;
        if (r0 < M) {
            __half2 h = __floats2half2_rn(acc[nt][0] * d0, acc[nt][1] * d0);
            *reinterpret_cast<__half2*>(&g_H16[(size_t)r0 * DIM + col]) = h;
        }
        if (r1 < M) {
            __half2 h = __floats2half2_rn(acc[nt][2] * d1, acc[nt][3] * d1);
            *reinterpret_cast<__half2*>(&g_H16[(size_t)r1 * DIM + col]) = h;
        }
    }
}

// ---------------- gather: AGG[d] = dinv[d] * (sum H'[src] + H'[d]) ------------
__device__ __forceinline__ void acc_row(float4& acc, uint2 raw) {
    float2 f0 = __half22float2(*reinterpret_cast<__half2*>(&raw.x));
    float2 f1 = __half22float2(*reinterpret_cast<__half2*>(&raw.y));
    acc.x += f0.x; acc.y += f0.y; acc.z += f1.x; acc.w += f1.y;
}
__global__ __launch_bounds__(256) void k_gather(int N) {
    int warp = (blockIdx.x * blockDim.x + threadIdx.x) >> 5;
    if (warp >= N) return;
    int lane = threadIdx.x & 31;

    const uint2* Hv = reinterpret_cast<const uint2*>(g_H16);
    int beg = g_rowptr[warp];
    int end = g_rowptr[warp + 1];

    float4 acc = make_float4(0.f, 0.f, 0.f, 0.f);
    acc_row(acc, Hv[(size_t)warp * 32 + lane]);

    int e = beg;
    for (; e + 4 <= end; e += 4) {
        int s0 = g_csr[e], s1 = g_csr[e + 1], s2 = g_csr[e + 2], s3 = g_csr[e + 3];
        uint2 r0 = Hv[(size_t)s0 * 32 + lane];
        uint2 r1 = Hv[(size_t)s1 * 32 + lane];
        uint2 r2 = Hv[(size_t)s2 * 32 + lane];
        uint2 r3 = Hv[(size_t)s3 * 32 + lane];
        acc_row(acc, r0); acc_row(acc, r1); acc_row(acc, r2); acc_row(acc, r3);
    }
    for (; e < end; e++)
        acc_row(acc, Hv[(size_t)g_csr[e] * 32 + lane]);

    float di = g_dinv[warp];
    __half2 h0 = __floats2half2_rn(acc.x * di, acc.y * di);
    __half2 h1 = __floats2half2_rn(acc.z * di, acc.w * di);
    uint2 outv;
    outv.x = *reinterpret_cast<u32*>(&h0);
    outv.y = *reinterpret_cast<u32*>(&h1);
    reinterpret_cast<uint2*>(g_AGG16)[(size_t)warp * 32 + lane] = outv;
}

// ---------------- pooling (run-length, batch sorted) --------------------------
__global__ void k_zero_pool() {
    int i = blockIdx.x * blockDim.x + threadIdx.x;
    if (i < NG * DIM) g_sums[i] = 0.f;
    if (i < NG) g_cnt[i] = 0.f;
}
#define PCHUNK 32
__global__ __launch_bounds__(256) void k_pool(const int* __restrict__ batch,
                                              const float* __restrict__ bias, int n) {
    int warp = (blockIdx.x * blockDim.x + threadIdx.x) >> 5;
    int lane = threadIdx.x & 31;
    int q = lane * 4;
    int n0 = warp * PCHUNK;
    if (n0 >= n) return;
    int n1 = min(n0 + PCHUNK, n);

    float b0 = bias[q], b1 = bias[q + 1], b2 = bias[q + 2], b3 = bias[q + 3];
    const uint2* Av = reinterpret_cast<const uint2*>(g_AGG16);

    float4 acc = make_float4(0.f, 0.f, 0.f, 0.f);
    float cnt = 0.f;
    int cur = batch[n0];
    for (int node = n0; node < n1; node++) {
        int bb = batch[node];
        if (bb != cur) {
            float* p = &g_sums[cur * DIM + q];
            asm volatile("red.global.add.v4.f32 [%0], {%1, %2, %3, %4};"
                         :: "l"(p), "f"(acc.x), "f"(acc.y), "f"(acc.z), "f"(acc.w) : "memory");
            if (lane == 0) atomicAdd(&g_cnt[cur], cnt);
            acc = make_float4(0.f, 0.f, 0.f, 0.f);
            cnt = 0.f;
            cur = bb;
        }
        uint2 raw = Av[(size_t)node * 32 + lane];
        float2 f0 = __half22float2(*reinterpret_cast<__half2*>(&raw.x));
        float2 f1 = __half22float2(*reinterpret_cast<__half2*>(&raw.y));
        acc.x += fmaxf(f0.x + b0, 0.f);
        acc.y += fmaxf(f0.y + b1, 0.f);
        acc.z += fmaxf(f1.x + b2, 0.f);
        acc.w += fmaxf(f1.y + b3, 0.f);
        cnt += 1.f;
    }
    float* p = &g_sums[cur * DIM + q];
    asm volatile("red.global.add.v4.f32 [%0], {%1, %2, %3, %4};"
                 :: "l"(p), "f"(acc.x), "f"(acc.y), "f"(acc.z), "f"(acc.w) : "memory");
    if (lane == 0) atomicAdd(&g_cnt[cur], cnt);
}

// ---------------- head --------------------------------------------------------
__global__ void k_lin1(const float* __restrict__ w1, const float* __restrict__ b1) {
    int g = blockIdx.x;
    int j = threadIdx.x;
    __shared__ float srow[DIM];
    float inv = 1.0f / fmaxf(g_cnt[g], 1.0f);
    srow[j] = g_sums[g * DIM + j] * inv;
    __syncthreads();
    float acc = b1[j];
#pragma unroll 8
    for (int k = 0; k < DIM; k++) acc += srow[k] * w1[k * DIM + j];
    g_G1[g * DIM + j] = fmaxf(acc, 0.f);
}
__global__ void k_head(const float* __restrict__ w2, const float* __restrict__ b2,
                       float* __restrict__ out) {
    int g = threadIdx.x;
    if (g >= NG) return;
    float l0 = b2[0], l1 = b2[1];
#pragma unroll 8
    for (int k = 0; k < DIM; k++) {
        float v = g_G1[g * DIM + k];
        l0 += v * w2[k * 2 + 0];
        l1 += v * w2[k * 2 + 1];
    }
    float m   = fmaxf(l0, l1);
    float lse = m + logf(expf(l0 - m) + expf(l1 - m));
    out[g * 2 + 0] = l0 - lse;
    out[g * 2 + 1] = l1 - lse;
}

// ---------------- launch ------------------------------------------------------
extern "C" void kernel_launch(void* const* d_in, const int* in_sizes, int n_in,
                              void* d_out, int out_size) {
    const float* x      = (const float*)d_in[0];
    const int*   ei     = (const int*)d_in[1];
    const int*   batch  = (const int*)d_in[2];
    const float* conv_w = (const float*)d_in[3];
    const float* conv_b = (const float*)d_in[4];
    const float* lin1_w = (const float*)d_in[5];
    const float* lin1_b = (const float*)d_in[6];
    const float* lin2_w = (const float*)d_in[7];
    const float* lin2_b = (const float*)d_in[8];
    float* out = (float*)d_out;

    int N = in_sizes[2];
    int E = in_sizes[1] / 2;
    const int* src = ei;
    const int* dst = ei + E;

    k_cvtw<<<(3 * DIM * DIM + 255) / 256, 256>>>(conv_w, 3 * DIM * DIM);
    k_zero_deg<<<(N + 255) / 256, 256>>>(N);
    k_deg<<<(E + 255) / 256, 256>>>(dst, E);

    int nb = (N + 511) / 512;
    k_scan1<<<nb, 512>>>(N);
    k_scan2<<<1, 256>>>(nb);
    k_scan3<<<nb, 512>>>(N, E);
    k_fill<<<(E + 255) / 256, 256>>>(src, dst, E);

    int gemm_blocks   = (N + 127) / 128;
    int gather_blocks = (N * 32 + 255) / 256;

    for (int l = 0; l < 3; l++) {
        const float* bias = (l > 0) ? (conv_b + (size_t)(l - 1) * DIM) : conv_b;
        k_gemm_mma<<<gemm_blocks, 256>>>(x, l, bias, l > 0 ? 1 : 0, N);
        k_gather<<<gather_blocks, 256>>>(N);
    }

    k_zero_pool<<<(NG * DIM + 255) / 256, 256>>>();
    int pool_warps = (N + PCHUNK - 1) / PCHUNK;
    k_pool<<<(pool_warps * 32 + 255) / 256, 256>>>(batch, conv_b + (size_t)2 * DIM, N);
    k_lin1<<<NG, DIM>>>(lin1_w, lin1_b);
    k_head<<<1, NG>>>(lin2_w, lin2_b, out);
}